// round 16
// baseline (speedup 1.0000x reference)
#include <cuda_runtime.h>
#include <cuda_bf16.h>
#include <math.h>
#include <cstdint>

#define D_FIX 256
#define C_MAX 50176
#define B_MAX 512
#define TS 272          // smem tile row stride in bytes (256 data + 16 pad)

// ---- device scratch (allocation-free: __device__ globals) ----
__device__ unsigned char g_tn8[(size_t)C_MAX * D_FIX];   // fp8 text (compact, x16)
__device__ unsigned char g_vn8[(size_t)B_MAX * D_FIX];   // fp8 visual (x16)
__device__ float g_denom[B_MAX];
__device__ float g_pos[B_MAX];
__device__ int   g_npos[B_MAX];

// ---------------------------------------------------------------------------
__device__ __forceinline__ unsigned smemu32(const void* p) {
    return (unsigned)__cvta_generic_to_shared(p);
}
#define CP_ASYNC16(dst, src) \
    asm volatile("cp.async.cg.shared.global [%0], [%1], 16;\n" :: "r"(dst), "l"(src))
#define CP_COMMIT()  asm volatile("cp.async.commit_group;\n")
#define CP_WAIT0()   asm volatile("cp.async.wait_group 0;\n" ::: "memory")

// pack 4 floats -> 4 e4m3 bytes (byte0 = a); cvt.e4m3x2 writes a b16 dest
__device__ __forceinline__ unsigned pack_e4m3x4(float a, float b, float c, float d) {
    unsigned short lo, hi;
    asm("cvt.rn.satfinite.e4m3x2.f32 %0, %1, %2;" : "=h"(lo) : "f"(b), "f"(a));
    asm("cvt.rn.satfinite.e4m3x2.f32 %0, %1, %2;" : "=h"(hi) : "f"(d), "f"(c));
    return ((unsigned)hi << 16) | (unsigned)lo;
}

__device__ __forceinline__ void mma_e4m3(float c[4], const unsigned a[4],
                                         unsigned b0, unsigned b1) {
    asm volatile(
        "mma.sync.aligned.m16n8k32.row.col.f32.e4m3.e4m3.f32 "
        "{%0,%1,%2,%3}, {%4,%5,%6,%7}, {%8,%9}, {%0,%1,%2,%3};\n"
        : "+f"(c[0]), "+f"(c[1]), "+f"(c[2]), "+f"(c[3])
        : "r"(a[0]), "r"(a[1]), "r"(a[2]), "r"(a[3]), "r"(b0), "r"(b1));
}

// ---------------------------------------------------------------------------
// pad-zero only (launched only when NL % 64 != 0)
__global__ void zero_pad_kernel(int padBytes, size_t padOff) {
    int i = blockIdx.x * blockDim.x + threadIdx.x;
    if (i < padBytes) g_tn8[padOff + i] = 0;
}

// Fused normalize, TWO rows per warp (MLP 4 per thread).
// rows [0, B)    : visual, no gather, eps=0, also zero per-row stats
// rows [B, B+NL) : text, gather via ids, eps=1e-6
__global__ void norm_fp8_fused(const float* __restrict__ vfeat,
                               const float* __restrict__ tfeat,
                               const int* __restrict__ ids,
                               int B, int NL) {
    int w = blockIdx.x * 8 + (threadIdx.x >> 5);
    int i0 = w * 2;
    int total = B + NL;
    if (i0 >= total) return;
    int lane = threadIdx.x & 31;

    const float4* src[2];
    unsigned* dst[2];
    float eps[2];
    bool act[2];
#pragma unroll
    for (int r = 0; r < 2; ++r) {
        int i = i0 + r;
        act[r] = (i < total);
        int ic = act[r] ? i : (total - 1);
        if (ic < B) {
            if (act[r] && lane == 0) { g_denom[ic] = 0.f; g_pos[ic] = 0.f; g_npos[ic] = 0; }
            src[r] = (const float4*)(vfeat + (size_t)ic * D_FIX);
            dst[r] = (unsigned*)g_vn8 + (size_t)ic * 64;
            eps[r] = 0.0f;
        } else {
            int j = ic - B;
            src[r] = (const float4*)(tfeat + (size_t)ids[j] * D_FIX);
            dst[r] = (unsigned*)g_tn8 + (size_t)j * 64;
            eps[r] = 1e-6f;
        }
    }

    // batched loads: 4 independent float4 per thread
    float4 t00 = src[0][lane], t01 = src[0][lane + 32];
    float4 t10 = src[1][lane], t11 = src[1][lane + 32];

    float ss0 = t00.x * t00.x + t00.y * t00.y + t00.z * t00.z + t00.w * t00.w
              + t01.x * t01.x + t01.y * t01.y + t01.z * t01.z + t01.w * t01.w;
    float ss1 = t10.x * t10.x + t10.y * t10.y + t10.z * t10.z + t10.w * t10.w
              + t11.x * t11.x + t11.y * t11.y + t11.z * t11.z + t11.w * t11.w;
#pragma unroll
    for (int o = 16; o > 0; o >>= 1) {
        ss0 += __shfl_xor_sync(0xffffffffu, ss0, o);
        ss1 += __shfl_xor_sync(0xffffffffu, ss1, o);
    }
    float inv0 = 16.0f / (eps[0] + sqrtf(ss0));
    float inv1 = 16.0f / (eps[1] + sqrtf(ss1));

    if (act[0]) {
        dst[0][lane]      = pack_e4m3x4(t00.x * inv0, t00.y * inv0, t00.z * inv0, t00.w * inv0);
        dst[0][lane + 32] = pack_e4m3x4(t01.x * inv0, t01.y * inv0, t01.z * inv0, t01.w * inv0);
    }
    if (act[1]) {
        dst[1][lane]      = pack_e4m3x4(t10.x * inv1, t10.y * inv1, t10.z * inv1, t10.w * inv1);
        dst[1][lane + 32] = pack_e4m3x4(t11.x * inv1, t11.y * inv1, t11.z * inv1, t11.w * inv1);
    }
}

// ---------------------------------------------------------------------------
// fp8 GEMM tile 128(M)x64(N), warp tile 32x32, full K=256 resident,
// 3 CTAs/SM, fused label gather (single MLP-32 batch) + loss epilogue.
// (byte-exact R12 configuration — measured 66.5 us, regs 80)
__global__ __launch_bounds__(256, 3)
void gemm_loss8(const int* __restrict__ label, const int* __restrict__ ids,
                int B, int C, int NL) {
    extern __shared__ unsigned char dynraw[];
    __shared__ float sdn[128], sps[128];
    __shared__ int sns[128];

    const int tid = threadIdx.x;
    const int cbase = blockIdx.x * 64;       // compact column base
    const int rbase = blockIdx.y * 128;

    unsigned base = (smemu32(dynraw) + 1023u) & ~1023u;
    const unsigned aB = base;
    const unsigned bB = base + 128u * TS;

    // async tile loads: A 128 rows (8 chunks/thread), B 64 rows (4 chunks/thread)
#pragma unroll
    for (int m = 0; m < 8; ++m) {
        int id = m * 256 + tid;
        int r = id >> 4, cb = id & 15;
        CP_ASYNC16(aB + (unsigned)(r * TS + cb * 16),
                   g_vn8 + (size_t)(rbase + r) * D_FIX + cb * 16);
    }
#pragma unroll
    for (int m = 0; m < 4; ++m) {
        int id = m * 256 + tid;
        int r = id >> 4, cb = id & 15;
        CP_ASYNC16(bB + (unsigned)(r * TS + cb * 16),
                   g_tn8 + (size_t)(cbase + r) * D_FIX + cb * 16);
    }
    CP_COMMIT();

    if (tid < 128) { sdn[tid] = 0.f; sps[tid] = 0.f; sns[tid] = 0; }

    const int lane = tid & 31, wid = tid >> 5;
    const int g = lane >> 2, tig = lane & 3;
    const int warp_m = wid & 3, warp_n = wid >> 2;   // 4 x 2
    const int grp = lane >> 3, rin = lane & 7;

    // ---- fused label gather: 8 cols x 4 rows, ONE batch of 32 loads ----
    int idv[8]; unsigned vbits = 0;
#pragma unroll
    for (int k = 0; k < 8; ++k) {
        int cl = warp_n * 32 + (k >> 1) * 8 + 2 * tig + (k & 1);
        int gc = cbase + cl;
        bool v = (gc < NL);
        if (v) vbits |= 1u << k;
        idv[k] = ids[v ? gc : (NL - 1)];
    }
    int labs[4][8];
#pragma unroll
    for (int r = 0; r < 4; ++r) {
        int rl = warp_m * 32 + (r >> 1) * 16 + (r & 1) * 8 + g;
        const int* lrow = label + (size_t)(rbase + rl) * C;
#pragma unroll
        for (int k = 0; k < 8; ++k) labs[r][k] = __ldg(&lrow[idv[k]]);
    }
    unsigned pm[4], nm[4];
#pragma unroll
    for (int r = 0; r < 4; ++r) {
        unsigned p = 0, n = 0;
#pragma unroll
        for (int k = 0; k < 8; ++k) {
            if ((vbits >> k) & 1) {
                if (labs[r][k] != 0) p |= 1u << k;
                else                 n |= 1u << k;
            }
        }
        pm[r] = p; nm[r] = n;
    }

    float acc[2][4][4];
#pragma unroll
    for (int i = 0; i < 2; i++)
#pragma unroll
        for (int j = 0; j < 4; j++)
#pragma unroll
            for (int k = 0; k < 4; k++) acc[i][j][k] = 0.f;

    CP_WAIT0();
    __syncthreads();

    unsigned aBase[2], bBase[2];
#pragma unroll
    for (int mt = 0; mt < 2; ++mt) {
        int rowA = warp_m * 32 + mt * 16 + (grp & 1) * 8 + rin;
        aBase[mt] = aB + (unsigned)(rowA * TS + (grp >> 1) * 16);
    }
#pragma unroll
    for (int p = 0; p < 2; ++p) {
        int rowB = warp_n * 32 + p * 16 + ((grp & 2) ? 8 : 0) + rin;
        bBase[p] = bB + (unsigned)(rowB * TS + (grp & 1) * 16);
    }

#pragma unroll
    for (int ks = 0; ks < 8; ++ks) {          // K = 8 x 32 fp8
        const unsigned kof = ks * 32;
        unsigned a[2][4], b[2][4];
#pragma unroll
        for (int mt = 0; mt < 2; ++mt)
            asm volatile(
                "ldmatrix.sync.aligned.m8n8.x4.shared.b16 {%0,%1,%2,%3}, [%4];\n"
                : "=r"(a[mt][0]), "=r"(a[mt][1]), "=r"(a[mt][2]), "=r"(a[mt][3])
                : "r"(aBase[mt] + kof));
#pragma unroll
        for (int p = 0; p < 2; ++p)
            asm volatile(
                "ldmatrix.sync.aligned.m8n8.x4.shared.b16 {%0,%1,%2,%3}, [%4];\n"
                : "=r"(b[p][0]), "=r"(b[p][1]), "=r"(b[p][2]), "=r"(b[p][3])
                : "r"(bBase[p] + kof));
#pragma unroll
        for (int p = 0; p < 2; ++p) {
            mma_e4m3(acc[0][2 * p],     a[0], b[p][0], b[p][2]);
            mma_e4m3(acc[1][2 * p],     a[1], b[p][0], b[p][2]);
            mma_e4m3(acc[0][2 * p + 1], a[0], b[p][1], b[p][3]);
            mma_e4m3(acc[1][2 * p + 1], a[1], b[p][1], b[p][3]);
        }
    }
    __syncthreads();

    // ---- epilogue: masked exp-sum / pos-sum / pos-count (S = acc / 256) ----
    const float sc = 1.0f / 256.0f;
#pragma unroll
    for (int mt = 0; mt < 2; ++mt) {
#pragma unroll
        for (int h = 0; h < 2; ++h) {
            int r = mt * 2 + h;
            int rl = warp_m * 32 + mt * 16 + h * 8 + g;
            unsigned pw = pm[r], nw = nm[r];
            float dsum = 0.f, psum = 0.f; int np = 0;
#pragma unroll
            for (int nt = 0; nt < 4; ++nt) {
#pragma unroll
                for (int q = 0; q < 2; ++q) {
                    int k = nt * 2 + q;
                    float s = acc[mt][nt][h * 2 + q] * sc;
                    if ((pw >> k) & 1) { psum += s; np += 1; }
                    else if ((nw >> k) & 1) dsum += __expf(s);
                }
            }
#pragma unroll
            for (int o = 1; o <= 2; o <<= 1) {
                dsum += __shfl_xor_sync(0xffffffffu, dsum, o);
                psum += __shfl_xor_sync(0xffffffffu, psum, o);
                np   += __shfl_xor_sync(0xffffffffu, np, o);
            }
            if (tig == 0) {
                atomicAdd(&sdn[rl], dsum);
                atomicAdd(&sps[rl], psum);
                atomicAdd(&sns[rl], np);
            }
        }
    }
    __syncthreads();
    if (tid < 128) {
        int grow = rbase + tid;
        if (grow < B) {
            atomicAdd(&g_denom[grow], sdn[tid]);
            atomicAdd(&g_pos[grow], sps[tid]);
            atomicAdd(&g_npos[grow], sns[tid]);
        }
    }
}

// ---------------------------------------------------------------------------
__global__ void finalize_kernel(float* __restrict__ out, int B) {
    __shared__ float red[4];
    int t = threadIdx.x;
    int lane = t & 31, w = t >> 5;
    float v = 0.f;
    for (int r = t; r < B; r += 128)
        v += __logf(g_denom[r]) - g_pos[r] / (float)g_npos[r];
#pragma unroll
    for (int o = 16; o > 0; o >>= 1) v += __shfl_xor_sync(0xffffffffu, v, o);
    if (lane == 0) red[w] = v;
    __syncthreads();
    if (t == 0) out[0] = (red[0] + red[1] + red[2] + red[3]) / (float)B;
}

// ---------------------------------------------------------------------------
extern "C" void kernel_launch(void* const* d_in, const int* in_sizes, int n_in,
                              void* d_out, int out_size) {
    const float* vfeat = (const float*)d_in[0];
    const float* tfeat = (const float*)d_in[1];
    const int*   label = (const int*)d_in[2];
    const int*   ids   = (const int*)d_in[3];
    (void)n_in; (void)out_size;

    double s0 = (double)in_sizes[0], s1 = (double)in_sizes[1], s2 = (double)in_sizes[2];
    int D = (int)(sqrt(s0 * s1 / s2) + 0.5);
    if (D <= 0) D = D_FIX;
    int B  = in_sizes[0] / D;
    int C  = in_sizes[1] / D;
    int NL = in_sizes[3];
    float* out = (float*)d_out;

    int ctiles = (NL + 63) / 64;            // 64-wide compact column tiles
    int padRows = ctiles * 64 - NL;
    int padBytes = padRows * D_FIX;
    size_t padOff = (size_t)NL * D_FIX;

    if (padBytes > 0)
        zero_pad_kernel<<<(padBytes + 255) / 256, 256>>>(padBytes, padOff);

    int nwarps = (B + NL + 1) / 2;
    norm_fp8_fused<<<(nwarps + 7) / 8, 256>>>(vfeat, tfeat, ids, B, NL);

    size_t smem_bytes = 1024 + (size_t)(128 + 64) * TS;   // R12 layout
    cudaFuncSetAttribute(gemm_loss8,
                         cudaFuncAttributeMaxDynamicSharedMemorySize,
                         (int)smem_bytes);
    dim3 grid(ctiles, (B + 127) / 128);
    gemm_loss8<<<grid, 256, smem_bytes>>>(label, ids, B, C, NL);

    finalize_kernel<<<1, 128>>>(out, B);
}